// round 16
// baseline (speedup 1.0000x reference)
#include <cuda_runtime.h>
#include <cuda_fp16.h>
#include <cstdint>

#define Nn 50000
#define Ee 800000
#define Ff 128
#define Bb 64
#define EPSBN 1e-5f
#define DEGCAP 64
#define NT64 782              // ceil(50000/64)

// ---------------- device scratch (zero-init; self-cleaning for graph replay) ----
__device__ __align__(16) float d_agg[Nn * Ff];   // mean-agg; layer2 GEMM writes pre2 here
__device__ __align__(16) float d_h[Nn * Ff];     // pre1 fp32 (pre-BN)
__device__ __align__(16) __half d_xh[Nn * Ff];   // fp16 copy of x (gather input)
__device__ __align__(16) __half d_hh[Nn * Ff];   // fp16 copy of pre1 (gather-2 input)
__device__ int   d_cnt_i[Nn];                    // degree; re-zeroed by layer-2 gather
__device__ int   d_esrc[Nn * DEGCAP];            // bucket adjacency
__device__ float d_sum[Ff];                      // re-zeroed by k_bnfin
__device__ float d_sqs[Ff];
__device__ __align__(16) float d_scale[Ff];
__device__ __align__(16) float d_shift[Ff];
__device__ __align__(16) float d_pool[Bb * Ff];  // re-zeroed by k_fin
__device__ float d_cnt[Bb];                      // re-zeroed by k_fin
// prepacked weight fragments (mma register order), tf32 hi only: [layer][32768]
__device__ __align__(16) float d_wfh[2][32768];

// ---------------- helpers ----------------
__device__ __forceinline__ uint32_t smem_u32(const void* p) {
    uint32_t a;
    asm("{ .reg .u64 t; cvta.to.shared.u64 t, %1; cvt.u32.u64 %0, t; }" : "=r"(a) : "l"(p));
    return a;
}
__device__ __forceinline__ float tf32r(float x) {
    uint32_t u;
    asm("cvt.rna.tf32.f32 %0, %1;" : "=r"(u) : "f"(x));
    return __uint_as_float(u);
}
__device__ __forceinline__ void mma1688(float* c, const uint4 a, const uint32_t b0, const uint32_t b1) {
    asm volatile("mma.sync.aligned.m16n8k8.row.col.f32.tf32.tf32.f32 "
        "{%0,%1,%2,%3}, {%4,%5,%6,%7}, {%8,%9}, {%0,%1,%2,%3};"
        : "+f"(c[0]), "+f"(c[1]), "+f"(c[2]), "+f"(c[3])
        : "r"(a.x), "r"(a.y), "r"(a.z), "r"(a.w), "r"(b0), "r"(b1));
}
#define CP_ASYNC16(sdst, gsrc) \
    asm volatile("cp.async.ca.shared.global [%0], [%1], 16;" :: "r"(sdst), "l"(gsrc) : "memory")
#define CP_COMMIT() asm volatile("cp.async.commit_group;" ::: "memory")
#define CP_WAIT0()  asm volatile("cp.async.wait_group 0;" ::: "memory")

// ---------------- bucket adjacency build ----------------
__global__ void k_fillb(const int* __restrict__ src, const int* __restrict__ dst) {
    int e = blockIdx.x * blockDim.x + threadIdx.x;
    if (e < Ee) {
        int d = dst[e];
        int pos = atomicAdd(&d_cnt_i[d], 1);
        if (pos < DEGCAP) d_esrc[d * DEGCAP + pos] = src[e];
    }
}

// ---------------- prep: weight fragments (tf32 hi) + fp16 copy of x --------------
__global__ void k_prep(const float* __restrict__ x,
                       const float* __restrict__ wl1, const float* __restrict__ wr1,
                       const float* __restrict__ wl2, const float* __restrict__ wr2) {
    int gid = blockIdx.x * 256 + threadIdx.x;
    if (blockIdx.x < 256) {
        int idx = gid;                  // 0..65535
        int layer = idx >> 15;
        int rem = idx & 32767;
        int pos = rem >> 2;
        int j = rem & 3;
        int K8 = pos >> 8;
        int p = (pos >> 5) & 7;
        int lane = pos & 31;
        int n8 = 2 * p + (j >> 1);
        int f = n8 * 8 + (lane >> 2);
        int k = K8 * 8 + (lane & 3) + (j & 1) * 4;
        const float* wl = layer ? wl2 : wl1;
        const float* wr = layer ? wr2 : wr1;
        float w = (k < 128) ? wl[k * 128 + f] : wr[(k - 128) * 128 + f];
        d_wfh[layer][rem] = tf32r(w);
    } else {
        int i = gid - 65536;            // float4 index into x
        if (i < Nn * 32) {
            float4 v = reinterpret_cast<const float4*>(x)[i];
            __half2* o = reinterpret_cast<__half2*>(d_xh) + 2 * i;
            o[0] = __floats2half2_rn(v.x, v.y);
            o[1] = __floats2half2_rn(v.z, v.w);
        }
    }
}

// ---------------- pull gather (fp16 inputs): warp per node, mean aggregation -----
__global__ void k_gather(int useH, int norm, int clearCnt) {
    int n = (blockIdx.x * blockDim.x + threadIdx.x) >> 5;
    int lane = threadIdx.x & 31;
    if (n >= Nn) return;
    const __half* feat = useH ? d_hh : d_xh;
    const uint2* f2 = reinterpret_cast<const uint2*>(feat);   // 32 uint2 per row
    const int deg = d_cnt_i[n];
    const int m = deg < DEGCAP ? deg : DEGCAP;
    const int* eb = d_esrc + n * DEGCAP;
    float4 acc = make_float4(0.f, 0.f, 0.f, 0.f);
    float4 sc, sh;
    if (norm) {
        sc = reinterpret_cast<const float4*>(d_scale)[lane];
        sh = reinterpret_cast<const float4*>(d_shift)[lane];
    }
#define CV4(u, v) { \
        __half2 _ha = *reinterpret_cast<__half2*>(&(u).x); \
        __half2 _hb = *reinterpret_cast<__half2*>(&(u).y); \
        float2 _pa = __half22float2(_ha); \
        float2 _pb = __half22float2(_hb); \
        v = make_float4(_pa.x, _pa.y, _pb.x, _pb.y); }
#define NORM4(v) if (norm) { \
        v.x = fmaxf(fmaf(v.x, sc.x, sh.x), 0.f); v.y = fmaxf(fmaf(v.y, sc.y, sh.y), 0.f); \
        v.z = fmaxf(fmaf(v.z, sc.z, sh.z), 0.f); v.w = fmaxf(fmaf(v.w, sc.w, sh.w), 0.f); }
    int j = 0;
    // 16-wide pass: maximize loads in flight (latency-bound for typical deg~16)
    for (; j + 16 <= m; j += 16) {
        uint2 u[16];
#pragma unroll
        for (int q = 0; q < 16; q++) u[q] = f2[eb[j + q] * 32 + lane];
#pragma unroll
        for (int q = 0; q < 16; q++) {
            float4 v;
            CV4(u[q], v)
            NORM4(v)
            acc.x += v.x; acc.y += v.y; acc.z += v.z; acc.w += v.w;
        }
    }
    for (; j + 8 <= m; j += 8) {
        uint2 u[8];
#pragma unroll
        for (int q = 0; q < 8; q++) u[q] = f2[eb[j + q] * 32 + lane];
#pragma unroll
        for (int q = 0; q < 8; q++) {
            float4 v;
            CV4(u[q], v)
            NORM4(v)
            acc.x += v.x; acc.y += v.y; acc.z += v.z; acc.w += v.w;
        }
    }
    for (; j < m; j++) {
        uint2 u0 = f2[eb[j] * 32 + lane];
        float4 v0;
        CV4(u0, v0)
        NORM4(v0)
        acc.x += v0.x; acc.y += v0.y; acc.z += v0.z; acc.w += v0.w;
    }
#undef NORM4
#undef CV4
    float inv = 1.f / fmaxf((float)deg, 1.f);
    acc.x *= inv; acc.y *= inv; acc.z *= inv; acc.w *= inv;
    reinterpret_cast<float4*>(d_agg)[n * 32 + lane] = acc;
    if (clearCnt && lane == 0) d_cnt_i[n] = 0;
}

// ---------------- tensor-core dual GEMM (mma.sync tf32, in-register A split) -----
// D = (Ah + Al) * Bh. A staged raw fp32, split to tf32 hi/lo in registers at mma.
// CTA tile = 64 nodes x 128 feats; smem ~50KB -> 3 CTAs/SM. One tile per CTA.
// smem float offsets
#define SM_BIAS  0
#define SM_SCALE 128
#define SM_SHIFT 256
#define SM_A     384
#define SM_B     (384 + 4096)
#define SMEM_TFL (384 + 12288)
#define SMEM_TB  (SMEM_TFL * 4)

__global__ void __launch_bounds__(256, 3)
k_gemmT(const float* __restrict__ xin, const float* __restrict__ bias, int layer) {
    extern __shared__ float sm[];
    uint4* sA = reinterpret_cast<uint4*>(sm + SM_A);
    uint4* sB = reinterpret_cast<uint4*>(sm + SM_B);

    const int tid = threadIdx.x;
    const int lane = tid & 31;
    const int w = tid >> 5;
    const int m16 = w & 3;            // node 16-block within tile
    const int fh  = w >> 2;           // feature half
    const int g = lane >> 2;
    const int tig = lane & 3;

    const float* aggp  = (const float*)d_agg;
    const float* selfp = (layer == 1) ? xin : (const float*)d_h;
    float* outp = (layer == 1) ? (float*)d_h : (float*)d_agg;
    const float* gbh = d_wfh[layer - 1];

    if (tid < 128) {
        sm[SM_BIAS + tid]  = bias[tid];
        sm[SM_SCALE + tid] = d_scale[tid];
        sm[SM_SHIFT + tid] = d_shift[tid];
    }

    const int base = blockIdx.x * 64;

    float acc[8][4];
    __syncthreads();
#pragma unroll
    for (int a = 0; a < 8; a++) {
        int f0 = fh * 64 + a * 8 + 2 * tig;
        float b0 = sm[SM_BIAS + f0];
        float b1 = sm[SM_BIAS + f0 + 1];
        acc[a][0] = b0; acc[a][1] = b1;
        acc[a][2] = b0; acc[a][3] = b1;
    }

    const uint32_t sBaddr = smem_u32(sB);

    for (int c = 0; c < 4; c++) {
        __syncthreads();
        // ---- B fragments via cp.async (raw copy, 8192 floats) ----
        {
            const float4* gh4 = reinterpret_cast<const float4*>(gbh + c * 8192);
            for (int i = tid; i < 2048; i += 256) {
                CP_ASYNC16(sBaddr + i * 16, (const void*)(gh4 + i));
            }
            CP_COMMIT();
        }
        // ---- stage A raw fp32 fragments: 1024 slots (k8[8], m16[4], lane[32]) ----
        for (int i = tid; i < 1024; i += 256) {
            int lp  = i & 31;
            int mm  = (i >> 5) & 3;
            int k8  = i >> 7;
            int n0 = base + mm * 16 + (lp >> 2);
            int kg = c * 64 + k8 * 8 + (lp & 3);
            float v[4];
#pragma unroll
            for (int q = 0; q < 4; q++) {
                int nn = n0 + (q & 1) * 8;
                int kk = kg + (q >> 1) * 4;
                float val = 0.f;
                if (nn < Nn) {
                    if (kk < 128) {
                        val = aggp[nn * 128 + kk];
                    } else {
                        val = selfp[nn * 128 + kk - 128];
                        if (layer == 2) {
                            val = fmaxf(fmaf(val, sm[SM_SCALE + kk - 128],
                                             sm[SM_SHIFT + kk - 128]), 0.f);
                        }
                    }
                }
                v[q] = val;
            }
            sA[i] = make_uint4(__float_as_uint(v[0]), __float_as_uint(v[1]),
                               __float_as_uint(v[2]), __float_as_uint(v[3]));
        }
        CP_WAIT0();
        __syncthreads();

        // ---- mma: 8 k8 steps; split A in registers; 2 precision sweeps ----
#pragma unroll 2
        for (int k8 = 0; k8 < 8; k8++) {
            uint4 ao = sA[(k8 * 4 + m16) * 32 + lane];
            float a0 = __uint_as_float(ao.x), a1 = __uint_as_float(ao.y);
            float a2 = __uint_as_float(ao.z), a3 = __uint_as_float(ao.w);
            float h0 = tf32r(a0), h1 = tf32r(a1), h2 = tf32r(a2), h3 = tf32r(a3);
            uint4 ah = make_uint4(__float_as_uint(h0), __float_as_uint(h1),
                                  __float_as_uint(h2), __float_as_uint(h3));
            uint4 al = make_uint4(__float_as_uint(tf32r(a0 - h0)),
                                  __float_as_uint(tf32r(a1 - h1)),
                                  __float_as_uint(tf32r(a2 - h2)),
                                  __float_as_uint(tf32r(a3 - h3)));
            uint4 bh[4];
#pragma unroll
            for (int pl = 0; pl < 4; pl++) {
                int p = fh * 4 + pl;
                bh[pl] = sB[(k8 * 8 + p) * 32 + lane];
            }
#pragma unroll
            for (int pl = 0; pl < 4; pl++) {
                mma1688(acc[2 * pl],     al, bh[pl].x, bh[pl].y);
                mma1688(acc[2 * pl + 1], al, bh[pl].z, bh[pl].w);
            }
#pragma unroll
            for (int pl = 0; pl < 4; pl++) {
                mma1688(acc[2 * pl],     ah, bh[pl].x, bh[pl].y);
                mma1688(acc[2 * pl + 1], ah, bh[pl].z, bh[pl].w);
            }
        }
    }

    // ---- epilogue: write D (and fp16 copy for layer-2 gather) ----
    int row0 = base + m16 * 16 + g;
    int row1 = row0 + 8;
#pragma unroll
    for (int a = 0; a < 8; a++) {
        int f0 = fh * 64 + a * 8 + 2 * tig;
        if (row0 < Nn) {
            *reinterpret_cast<float2*>(&outp[row0 * 128 + f0]) =
                make_float2(acc[a][0], acc[a][1]);
            if (layer == 1)
                *reinterpret_cast<__half2*>(&d_hh[row0 * 128 + f0]) =
                    __floats2half2_rn(acc[a][0], acc[a][1]);
        }
        if (row1 < Nn) {
            *reinterpret_cast<float2*>(&outp[row1 * 128 + f0]) =
                make_float2(acc[a][2], acc[a][3]);
            if (layer == 1)
                *reinterpret_cast<__half2*>(&d_hh[row1 * 128 + f0]) =
                    __floats2half2_rn(acc[a][2], acc[a][3]);
        }
    }
}

// ---------------- BN stats over pre-activations ----------------------------------
__global__ void k_bnstat(int layer) {
    const float* src = (layer == 1) ? (const float*)d_h : (const float*)d_agg;
    __shared__ float s1[128], s2[128];
    int tid = threadIdx.x;                 // 256
    if (tid < 128) { s1[tid] = 0.f; s2[tid] = 0.f; }
    __syncthreads();
    int f = tid & 127, h = tid >> 7;
    float a = 0.f, b = 0.f;
    for (int n = blockIdx.x * 2 + h; n < Nn; n += gridDim.x * 2) {
        float v = src[n * 128 + f];
        a += v; b += v * v;
    }
    atomicAdd(&s1[f], a);
    atomicAdd(&s2[f], b);
    __syncthreads();
    if (tid < 128) {
        atomicAdd(&d_sum[tid], s1[tid]);
        atomicAdd(&d_sqs[tid], s2[tid]);
    }
}

// ---------------- BN finalize (resets stats for next layer / replay) -------------
__global__ void k_bnfin(const float* __restrict__ g, const float* __restrict__ beta) {
    int fidx = threadIdx.x;
    float mu = d_sum[fidx] * (1.0f / Nn);
    float var = d_sqs[fidx] * (1.0f / Nn) - mu * mu;
    float sc = g[fidx] * rsqrtf(var + EPSBN);
    d_scale[fidx] = sc;
    d_shift[fidx] = beta[fidx] - mu * sc;
    d_sum[fidx] = 0.f;
    d_sqs[fidx] = 0.f;
}

// ---------------- fused norm+relu+pool: warp per node ----------------------------
__global__ void k_pool(const int* __restrict__ batch) {
    int n = (blockIdx.x * blockDim.x + threadIdx.x) >> 5;
    int lane = threadIdx.x & 31;
    if (n >= Nn) return;
    int b = batch[n];
    float4 v = reinterpret_cast<const float4*>(d_agg)[n * 32 + lane];
    float4 sc = reinterpret_cast<const float4*>(d_scale)[lane];
    float4 sh = reinterpret_cast<const float4*>(d_shift)[lane];
    v.x = fmaxf(fmaf(v.x, sc.x, sh.x), 0.f);
    v.y = fmaxf(fmaf(v.y, sc.y, sh.y), 0.f);
    v.z = fmaxf(fmaf(v.z, sc.z, sh.z), 0.f);
    v.w = fmaxf(fmaf(v.w, sc.w, sh.w), 0.f);
    float* pp = d_pool + b * 128 + lane * 4;
    asm volatile("red.global.add.v4.f32 [%0], {%1,%2,%3,%4};"
                 :: "l"(pp), "f"(v.x), "f"(v.y), "f"(v.z), "f"(v.w) : "memory");
    if (lane == 0) atomicAdd(d_cnt + b, 1.0f);
}

// ---------------- finalize (single block; self-cleans d_pool/d_cnt) --------------
__global__ void k_fin(float* __restrict__ out) {
    int tid = threadIdx.x;
    for (int i = tid; i < Bb * Ff; i += 1024) {
        float c = d_cnt[i >> 7];
        out[i] = d_pool[i] / fmaxf(c, 1.f);
    }
    __syncthreads();
    for (int i = tid; i < Bb * Ff; i += 1024) d_pool[i] = 0.f;
    if (tid < Bb) d_cnt[tid] = 0.f;
}

// ---------------- launcher --------------------------------------------------------
extern "C" void kernel_launch(void* const* d_in, const int* in_sizes, int n_in,
                              void* d_out, int out_size) {
    const float* x     = (const float*)d_in[0];
    const int*   ei    = (const int*)d_in[1];
    const int*   batch = (const int*)d_in[2];
    const float* wl1   = (const float*)d_in[3];
    const float* bl1   = (const float*)d_in[4];
    const float* wr1   = (const float*)d_in[5];
    const float* g1    = (const float*)d_in[6];
    const float* beta1 = (const float*)d_in[7];
    const float* wl2   = (const float*)d_in[8];
    const float* bl2   = (const float*)d_in[9];
    const float* wr2   = (const float*)d_in[10];
    const float* g2    = (const float*)d_in[11];
    const float* beta2 = (const float*)d_in[12];
    const int* src = ei;
    const int* dst = ei + Ee;
    float* out = (float*)d_out;

    cudaFuncSetAttribute(k_gemmT, cudaFuncAttributeMaxDynamicSharedMemorySize, SMEM_TB);

    const int edgeBlocks = (Ee + 255) / 256;
    const int gatherBlocks = (Nn * 32 + 255) / 256;
    const int prepBlocks = 256 + (Nn * 32 + 255) / 256;

    k_fillb<<<edgeBlocks, 256>>>(src, dst);                    // 0
    k_prep<<<prepBlocks, 256>>>(x, wl1, wr1, wl2, wr2);        // 1

    // ---- layer 1 ----
    k_gather<<<gatherBlocks, 256>>>(0, 0, 0);                  // 2
    k_gemmT<<<NT64, 256, SMEM_TB>>>(x, bl1, 1);                // 3  <- profiled
    k_bnstat<<<148, 256>>>(1);                                 // 4
    k_bnfin<<<1, 128>>>(g1, beta1);                            // 5

    // ---- layer 2 ----
    k_gather<<<gatherBlocks, 256>>>(1, 1, 1);                  // 6
    k_gemmT<<<NT64, 256, SMEM_TB>>>(x, bl2, 2);                // 7
    k_bnstat<<<148, 256>>>(2);                                 // 8
    k_bnfin<<<1, 128>>>(g2, beta2);                            // 9

    // ---- pool ----
    k_pool<<<(Nn + 7) / 8, 256>>>(batch);                      // 10
    k_fin<<<1, 1024>>>(out);                                   // 11
}

// round 17
// speedup vs baseline: 1.2628x; 1.2628x over previous
#include <cuda_runtime.h>
#include <cuda_fp16.h>
#include <cstdint>

#define Nn 50000
#define Ee 800000
#define Ff 128
#define Bb 64
#define EPSBN 1e-5f
#define DEGCAP 64
#define NT64 782              // ceil(50000/64)

// ---------------- device scratch (zero-init; self-cleaning for graph replay) ----
__device__ __align__(16) float d_agg[Nn * Ff];   // mean-agg; layer2 GEMM writes pre2 here
__device__ __align__(16) float d_h[Nn * Ff];     // pre1 fp32 (pre-BN)
__device__ __align__(16) __half d_xh[Nn * Ff];   // fp16 copy of x (gather input)
__device__ __align__(16) __half d_hh[Nn * Ff];   // fp16 copy of pre1 (gather-2 input)
__device__ int   d_cnt_i[Nn];                    // degree; re-zeroed by layer-2 gather
__device__ int   d_esrc[Nn * DEGCAP];            // bucket adjacency
__device__ float d_sum[Ff];                      // re-zeroed by k_bnfin
__device__ float d_sqs[Ff];
__device__ __align__(16) float d_scale[Ff];
__device__ __align__(16) float d_shift[Ff];
__device__ __align__(16) float d_pool[Bb * Ff];  // re-zeroed by k_fin
__device__ float d_cnt[Bb];                      // re-zeroed by k_fin
// prepacked weight fragments (mma register order), tf32 hi only: [layer][32768]
__device__ __align__(16) float d_wfh[2][32768];

// ---------------- helpers ----------------
__device__ __forceinline__ uint32_t smem_u32(const void* p) {
    uint32_t a;
    asm("{ .reg .u64 t; cvta.to.shared.u64 t, %1; cvt.u32.u64 %0, t; }" : "=r"(a) : "l"(p));
    return a;
}
__device__ __forceinline__ float tf32r(float x) {
    uint32_t u;
    asm("cvt.rna.tf32.f32 %0, %1;" : "=r"(u) : "f"(x));
    return __uint_as_float(u);
}
__device__ __forceinline__ void mma1688(float* c, const uint4 a, const uint32_t b0, const uint32_t b1) {
    asm volatile("mma.sync.aligned.m16n8k8.row.col.f32.tf32.tf32.f32 "
        "{%0,%1,%2,%3}, {%4,%5,%6,%7}, {%8,%9}, {%0,%1,%2,%3};"
        : "+f"(c[0]), "+f"(c[1]), "+f"(c[2]), "+f"(c[3])
        : "r"(a.x), "r"(a.y), "r"(a.z), "r"(a.w), "r"(b0), "r"(b1));
}
#define CP_ASYNC16(sdst, gsrc) \
    asm volatile("cp.async.ca.shared.global [%0], [%1], 16;" :: "r"(sdst), "l"(gsrc) : "memory")
#define CP_COMMIT() asm volatile("cp.async.commit_group;" ::: "memory")
#define CP_WAIT0()  asm volatile("cp.async.wait_group 0;" ::: "memory")

// ---------------- bucket adjacency build ----------------
__global__ void k_fillb(const int* __restrict__ src, const int* __restrict__ dst) {
    int e = blockIdx.x * blockDim.x + threadIdx.x;
    if (e < Ee) {
        int d = dst[e];
        int pos = atomicAdd(&d_cnt_i[d], 1);
        if (pos < DEGCAP) d_esrc[d * DEGCAP + pos] = src[e];
    }
}

// ---------------- prep: weight fragments (tf32 hi) + fp16 copy of x --------------
__global__ void k_prep(const float* __restrict__ x,
                       const float* __restrict__ wl1, const float* __restrict__ wr1,
                       const float* __restrict__ wl2, const float* __restrict__ wr2) {
    int gid = blockIdx.x * 256 + threadIdx.x;
    if (blockIdx.x < 256) {
        int idx = gid;                  // 0..65535
        int layer = idx >> 15;
        int rem = idx & 32767;
        int pos = rem >> 2;
        int j = rem & 3;
        int K8 = pos >> 8;
        int p = (pos >> 5) & 7;
        int lane = pos & 31;
        int n8 = 2 * p + (j >> 1);
        int f = n8 * 8 + (lane >> 2);
        int k = K8 * 8 + (lane & 3) + (j & 1) * 4;
        const float* wl = layer ? wl2 : wl1;
        const float* wr = layer ? wr2 : wr1;
        float w = (k < 128) ? wl[k * 128 + f] : wr[(k - 128) * 128 + f];
        d_wfh[layer][rem] = tf32r(w);
    } else {
        int i = gid - 65536;            // float4 index into x
        if (i < Nn * 32) {
            float4 v = reinterpret_cast<const float4*>(x)[i];
            __half2* o = reinterpret_cast<__half2*>(d_xh) + 2 * i;
            o[0] = __floats2half2_rn(v.x, v.y);
            o[1] = __floats2half2_rn(v.z, v.w);
        }
    }
}

// ---------------- pull gather (fp16 inputs): warp per node, mean aggregation -----
__global__ void k_gather(int useH, int norm, int clearCnt) {
    int n = (blockIdx.x * blockDim.x + threadIdx.x) >> 5;
    int lane = threadIdx.x & 31;
    if (n >= Nn) return;
    const __half* feat = useH ? d_hh : d_xh;
    const uint2* f2 = reinterpret_cast<const uint2*>(feat);   // 32 uint2 per row
    const int deg = d_cnt_i[n];
    const int m = deg < DEGCAP ? deg : DEGCAP;
    const int* eb = d_esrc + n * DEGCAP;
    float4 acc = make_float4(0.f, 0.f, 0.f, 0.f);
    float4 sc, sh;
    if (norm) {
        sc = reinterpret_cast<const float4*>(d_scale)[lane];
        sh = reinterpret_cast<const float4*>(d_shift)[lane];
    }
#define CV4(u, v) { \
        __half2 _ha = *reinterpret_cast<__half2*>(&(u).x); \
        __half2 _hb = *reinterpret_cast<__half2*>(&(u).y); \
        float2 _pa = __half22float2(_ha); \
        float2 _pb = __half22float2(_hb); \
        v = make_float4(_pa.x, _pa.y, _pb.x, _pb.y); }
#define NORM4(v) if (norm) { \
        v.x = fmaxf(fmaf(v.x, sc.x, sh.x), 0.f); v.y = fmaxf(fmaf(v.y, sc.y, sh.y), 0.f); \
        v.z = fmaxf(fmaf(v.z, sc.z, sh.z), 0.f); v.w = fmaxf(fmaf(v.w, sc.w, sh.w), 0.f); }
    int j = 0;
    // 16-wide pass: maximize loads in flight (latency-bound for typical deg~16)
    for (; j + 16 <= m; j += 16) {
        uint2 u[16];
#pragma unroll
        for (int q = 0; q < 16; q++) u[q] = f2[eb[j + q] * 32 + lane];
#pragma unroll
        for (int q = 0; q < 16; q++) {
            float4 v;
            CV4(u[q], v)
            NORM4(v)
            acc.x += v.x; acc.y += v.y; acc.z += v.z; acc.w += v.w;
        }
    }
    for (; j + 8 <= m; j += 8) {
        uint2 u[8];
#pragma unroll
        for (int q = 0; q < 8; q++) u[q] = f2[eb[j + q] * 32 + lane];
#pragma unroll
        for (int q = 0; q < 8; q++) {
            float4 v;
            CV4(u[q], v)
            NORM4(v)
            acc.x += v.x; acc.y += v.y; acc.z += v.z; acc.w += v.w;
        }
    }
    for (; j < m; j++) {
        uint2 u0 = f2[eb[j] * 32 + lane];
        float4 v0;
        CV4(u0, v0)
        NORM4(v0)
        acc.x += v0.x; acc.y += v0.y; acc.z += v0.z; acc.w += v0.w;
    }
#undef NORM4
#undef CV4
    float inv = 1.f / fmaxf((float)deg, 1.f);
    acc.x *= inv; acc.y *= inv; acc.z *= inv; acc.w *= inv;
    reinterpret_cast<float4*>(d_agg)[n * 32 + lane] = acc;
    if (clearCnt && lane == 0) d_cnt_i[n] = 0;
}

// ---------------- tensor-core dual GEMM + shfl-reduced BN stats ------------------
// D = (Ah + Al) * Bh (tf32 split in registers). BN sum/sumsq reduced with
// __shfl_xor across the 8 lanes sharing tig (covers the warp's 16 rows), then
// 4 conflict-free lanes/warp do smem atomics; one global atomic/feature/CTA.
// CTA tile = 64 nodes x 128 feats; smem ~50KB -> 3 CTAs/SM. One tile per CTA.
// smem float offsets
#define SM_BIAS  0
#define SM_SCALE 128
#define SM_SHIFT 256
#define SM_SUM   384
#define SM_SQ    512
#define SM_A     640
#define SM_B     (640 + 4096)
#define SMEM_TFL (640 + 12288)
#define SMEM_TB  (SMEM_TFL * 4)

__global__ void __launch_bounds__(256, 3)
k_gemmT(const float* __restrict__ xin, const float* __restrict__ bias, int layer) {
    extern __shared__ float sm[];
    uint4* sA = reinterpret_cast<uint4*>(sm + SM_A);
    uint4* sB = reinterpret_cast<uint4*>(sm + SM_B);

    const int tid = threadIdx.x;
    const int lane = tid & 31;
    const int w = tid >> 5;
    const int m16 = w & 3;            // node 16-block within tile
    const int fh  = w >> 2;           // feature half
    const int g = lane >> 2;
    const int tig = lane & 3;

    const float* aggp  = (const float*)d_agg;
    const float* selfp = (layer == 1) ? xin : (const float*)d_h;
    float* outp = (layer == 1) ? (float*)d_h : (float*)d_agg;
    const float* gbh = d_wfh[layer - 1];

    if (tid < 128) {
        sm[SM_BIAS + tid]  = bias[tid];
        sm[SM_SCALE + tid] = d_scale[tid];
        sm[SM_SHIFT + tid] = d_shift[tid];
        sm[SM_SUM + tid] = 0.f;
        sm[SM_SQ + tid]  = 0.f;
    }

    const int base = blockIdx.x * 64;

    float acc[8][4];
    __syncthreads();
#pragma unroll
    for (int a = 0; a < 8; a++) {
        int f0 = fh * 64 + a * 8 + 2 * tig;
        float b0 = sm[SM_BIAS + f0];
        float b1 = sm[SM_BIAS + f0 + 1];
        acc[a][0] = b0; acc[a][1] = b1;
        acc[a][2] = b0; acc[a][3] = b1;
    }

    const uint32_t sBaddr = smem_u32(sB);

    for (int c = 0; c < 4; c++) {
        __syncthreads();
        // ---- B fragments via cp.async (raw copy, 8192 floats) ----
        {
            const float4* gh4 = reinterpret_cast<const float4*>(gbh + c * 8192);
            for (int i = tid; i < 2048; i += 256) {
                CP_ASYNC16(sBaddr + i * 16, (const void*)(gh4 + i));
            }
            CP_COMMIT();
        }
        // ---- stage A raw fp32 fragments: 1024 slots (k8[8], m16[4], lane[32]) ----
        for (int i = tid; i < 1024; i += 256) {
            int lp  = i & 31;
            int mm  = (i >> 5) & 3;
            int k8  = i >> 7;
            int n0 = base + mm * 16 + (lp >> 2);
            int kg = c * 64 + k8 * 8 + (lp & 3);
            float v[4];
#pragma unroll
            for (int q = 0; q < 4; q++) {
                int nn = n0 + (q & 1) * 8;
                int kk = kg + (q >> 1) * 4;
                float val = 0.f;
                if (nn < Nn) {
                    if (kk < 128) {
                        val = aggp[nn * 128 + kk];
                    } else {
                        val = selfp[nn * 128 + kk - 128];
                        if (layer == 2) {
                            val = fmaxf(fmaf(val, sm[SM_SCALE + kk - 128],
                                             sm[SM_SHIFT + kk - 128]), 0.f);
                        }
                    }
                }
                v[q] = val;
            }
            sA[i] = make_uint4(__float_as_uint(v[0]), __float_as_uint(v[1]),
                               __float_as_uint(v[2]), __float_as_uint(v[3]));
        }
        CP_WAIT0();
        __syncthreads();

        // ---- mma: 8 k8 steps; split A in registers; 2 precision sweeps ----
#pragma unroll 2
        for (int k8 = 0; k8 < 8; k8++) {
            uint4 ao = sA[(k8 * 4 + m16) * 32 + lane];
            float a0 = __uint_as_float(ao.x), a1 = __uint_as_float(ao.y);
            float a2 = __uint_as_float(ao.z), a3 = __uint_as_float(ao.w);
            float h0 = tf32r(a0), h1 = tf32r(a1), h2 = tf32r(a2), h3 = tf32r(a3);
            uint4 ah = make_uint4(__float_as_uint(h0), __float_as_uint(h1),
                                  __float_as_uint(h2), __float_as_uint(h3));
            uint4 al = make_uint4(__float_as_uint(tf32r(a0 - h0)),
                                  __float_as_uint(tf32r(a1 - h1)),
                                  __float_as_uint(tf32r(a2 - h2)),
                                  __float_as_uint(tf32r(a3 - h3)));
            uint4 bh[4];
#pragma unroll
            for (int pl = 0; pl < 4; pl++) {
                int p = fh * 4 + pl;
                bh[pl] = sB[(k8 * 8 + p) * 32 + lane];
            }
#pragma unroll
            for (int pl = 0; pl < 4; pl++) {
                mma1688(acc[2 * pl],     al, bh[pl].x, bh[pl].y);
                mma1688(acc[2 * pl + 1], al, bh[pl].z, bh[pl].w);
            }
#pragma unroll
            for (int pl = 0; pl < 4; pl++) {
                mma1688(acc[2 * pl],     ah, bh[pl].x, bh[pl].y);
                mma1688(acc[2 * pl + 1], ah, bh[pl].z, bh[pl].w);
            }
        }
    }

    // ---- epilogue: write D (+fp16 copy for layer-2 gather) + shfl-reduced stats ----
    int row0 = base + m16 * 16 + g;
    int row1 = row0 + 8;
#pragma unroll
    for (int a = 0; a < 8; a++) {
        int f0 = fh * 64 + a * 8 + 2 * tig;
        float s0 = 0.f, s1 = 0.f, q0 = 0.f, q1 = 0.f;
        if (row0 < Nn) {
            *reinterpret_cast<float2*>(&outp[row0 * 128 + f0]) =
                make_float2(acc[a][0], acc[a][1]);
            if (layer == 1)
                *reinterpret_cast<__half2*>(&d_hh[row0 * 128 + f0]) =
                    __floats2half2_rn(acc[a][0], acc[a][1]);
            s0 += acc[a][0]; q0 += acc[a][0] * acc[a][0];
            s1 += acc[a][1]; q1 += acc[a][1] * acc[a][1];
        }
        if (row1 < Nn) {
            *reinterpret_cast<float2*>(&outp[row1 * 128 + f0]) =
                make_float2(acc[a][2], acc[a][3]);
            if (layer == 1)
                *reinterpret_cast<__half2*>(&d_hh[row1 * 128 + f0]) =
                    __floats2half2_rn(acc[a][2], acc[a][3]);
            s0 += acc[a][2]; q0 += acc[a][2] * acc[a][2];
            s1 += acc[a][3]; q1 += acc[a][3] * acc[a][3];
        }
        // reduce over the 8 lanes sharing tig (g = 0..7): covers all 16 rows
#pragma unroll
        for (int msk = 4; msk <= 16; msk <<= 1) {
            s0 += __shfl_xor_sync(0xffffffff, s0, msk);
            s1 += __shfl_xor_sync(0xffffffff, s1, msk);
            q0 += __shfl_xor_sync(0xffffffff, q0, msk);
            q1 += __shfl_xor_sync(0xffffffff, q1, msk);
        }
        if (g == 0) {   // 4 lanes, distinct feature pairs -> conflict-free atomics
            atomicAdd(&sm[SM_SUM + f0], s0);
            atomicAdd(&sm[SM_SUM + f0 + 1], s1);
            atomicAdd(&sm[SM_SQ + f0], q0);
            atomicAdd(&sm[SM_SQ + f0 + 1], q1);
        }
    }
    __syncthreads();
    if (tid < 128) {
        atomicAdd(&d_sum[tid], sm[SM_SUM + tid]);
        atomicAdd(&d_sqs[tid], sm[SM_SQ + tid]);
    }
}

// ---------------- BN finalize (resets stats for next layer / replay) -------------
__global__ void k_bnfin(const float* __restrict__ g, const float* __restrict__ beta) {
    int fidx = threadIdx.x;
    float mu = d_sum[fidx] * (1.0f / Nn);
    float var = d_sqs[fidx] * (1.0f / Nn) - mu * mu;
    float sc = g[fidx] * rsqrtf(var + EPSBN);
    d_scale[fidx] = sc;
    d_shift[fidx] = beta[fidx] - mu * sc;
    d_sum[fidx] = 0.f;
    d_sqs[fidx] = 0.f;
}

// ---------------- fused norm+relu+pool: warp per node ----------------------------
__global__ void k_pool(const int* __restrict__ batch) {
    int n = (blockIdx.x * blockDim.x + threadIdx.x) >> 5;
    int lane = threadIdx.x & 31;
    if (n >= Nn) return;
    int b = batch[n];
    float4 v = reinterpret_cast<const float4*>(d_agg)[n * 32 + lane];
    float4 sc = reinterpret_cast<const float4*>(d_scale)[lane];
    float4 sh = reinterpret_cast<const float4*>(d_shift)[lane];
    v.x = fmaxf(fmaf(v.x, sc.x, sh.x), 0.f);
    v.y = fmaxf(fmaf(v.y, sc.y, sh.y), 0.f);
    v.z = fmaxf(fmaf(v.z, sc.z, sh.z), 0.f);
    v.w = fmaxf(fmaf(v.w, sc.w, sh.w), 0.f);
    float* pp = d_pool + b * 128 + lane * 4;
    asm volatile("red.global.add.v4.f32 [%0], {%1,%2,%3,%4};"
                 :: "l"(pp), "f"(v.x), "f"(v.y), "f"(v.z), "f"(v.w) : "memory");
    if (lane == 0) atomicAdd(d_cnt + b, 1.0f);
}

// ---------------- finalize (single block; self-cleans d_pool/d_cnt) --------------
__global__ void k_fin(float* __restrict__ out) {
    int tid = threadIdx.x;
    for (int i = tid; i < Bb * Ff; i += 1024) {
        float c = d_cnt[i >> 7];
        out[i] = d_pool[i] / fmaxf(c, 1.f);
    }
    __syncthreads();
    for (int i = tid; i < Bb * Ff; i += 1024) d_pool[i] = 0.f;
    if (tid < Bb) d_cnt[tid] = 0.f;
}

// ---------------- launcher --------------------------------------------------------
extern "C" void kernel_launch(void* const* d_in, const int* in_sizes, int n_in,
                              void* d_out, int out_size) {
    const float* x     = (const float*)d_in[0];
    const int*   ei    = (const int*)d_in[1];
    const int*   batch = (const int*)d_in[2];
    const float* wl1   = (const float*)d_in[3];
    const float* bl1   = (const float*)d_in[4];
    const float* wr1   = (const float*)d_in[5];
    const float* g1    = (const float*)d_in[6];
    const float* beta1 = (const float*)d_in[7];
    const float* wl2   = (const float*)d_in[8];
    const float* bl2   = (const float*)d_in[9];
    const float* wr2   = (const float*)d_in[10];
    const float* g2    = (const float*)d_in[11];
    const float* beta2 = (const float*)d_in[12];
    const int* src = ei;
    const int* dst = ei + Ee;
    float* out = (float*)d_out;

    cudaFuncSetAttribute(k_gemmT, cudaFuncAttributeMaxDynamicSharedMemorySize, SMEM_TB);

    const int edgeBlocks = (Ee + 255) / 256;
    const int gatherBlocks = (Nn * 32 + 255) / 256;
    const int prepBlocks = 256 + (Nn * 32 + 255) / 256;

    k_fillb<<<edgeBlocks, 256>>>(src, dst);                    // 0
    k_prep<<<prepBlocks, 256>>>(x, wl1, wr1, wl2, wr2);        // 1

    // ---- layer 1 ----
    k_gather<<<gatherBlocks, 256>>>(0, 0, 0);                  // 2
    k_gemmT<<<NT64, 256, SMEM_TB>>>(x, bl1, 1);                // 3  <- profiled
    k_bnfin<<<1, 128>>>(g1, beta1);                            // 4

    // ---- layer 2 ----
    k_gather<<<gatherBlocks, 256>>>(1, 1, 1);                  // 5
    k_gemmT<<<NT64, 256, SMEM_TB>>>(x, bl2, 2);                // 6
    k_bnfin<<<1, 128>>>(g2, beta2);                            // 7

    // ---- pool ----
    k_pool<<<(Nn + 7) / 8, 256>>>(batch);                      // 8
    k_fin<<<1, 1024>>>(out);                                   // 9
}